// round 5
// baseline (speedup 1.0000x reference)
#include <cuda_runtime.h>

#define N_NODES 50000
#define N_EDGES 800000
#define SCAN_T  1024
#define CHUNK   ((N_NODES + SCAN_T - 1) / SCAN_T)   // 49

// ---------------- scratch (no allocation allowed) ----------------
__device__ float g_agg[N_NODES * 128];   // normalized aggregation (both layers)
__device__ float g_h  [N_NODES * 128];   // layer-1 hidden activations
__device__ int   g_deg[N_NODES];         // in-degree
__device__ int   g_off[N_NODES + 1];     // CSR offsets (by dst)
__device__ int   g_cur[N_NODES];         // fill cursors
__device__ int   g_elist[N_EDGES];       // src list grouped by dst
__device__ float g_B1d[256 * 256];       // [W1l;W1r]^T k-major, DUPLICATED cols
__device__ float g_B2d[256 * 128];       // [W2l;W2r]^T k-major, DUPLICATED cols

// ---------------- weight prep: concatenated k-major B, each value dup'd ----
__global__ void prep_weights(const float* __restrict__ W1l, const float* __restrict__ W1r,
                             const float* __restrict__ W2l, const float* __restrict__ W2r) {
    int t = blockIdx.x * blockDim.x + threadIdx.x;
    if (t < 256 * 128) {
        int k = t >> 7, o = t & 127;
        float v = (k < 128) ? W1l[o * 128 + k] : W1r[o * 128 + (k - 128)];
        g_B1d[k * 256 + 2 * o] = v;
        g_B1d[k * 256 + 2 * o + 1] = v;
    } else if (t < 256 * 128 + 256 * 64) {
        int t2 = t - 256 * 128;
        int k = t2 >> 6, o = t2 & 63;
        float v = (k < 128) ? W2l[o * 128 + k] : W2r[o * 128 + (k - 128)];
        g_B2d[k * 128 + 2 * o] = v;
        g_B2d[k * 128 + 2 * o + 1] = v;
    }
}

// ---------------- CSR build ----------------
__global__ void zero_deg() {
    int t = blockIdx.x * blockDim.x + threadIdx.x;
    if (t < N_NODES) g_deg[t] = 0;
}

__global__ void count_deg(const int* __restrict__ ei) {
    int e = blockIdx.x * blockDim.x + threadIdx.x;
    if (e < N_EDGES) atomicAdd(&g_deg[__ldg(&ei[N_EDGES + e])], 1);
}

__global__ void scan_deg() {
    __shared__ int ssum[SCAN_T];
    int t = threadIdx.x;
    int start = t * CHUNK;
    int s = 0;
    for (int i = 0; i < CHUNK; i++) {
        int n = start + i;
        if (n < N_NODES) s += g_deg[n];
    }
    ssum[t] = s;
    __syncthreads();
    // Hillis-Steele inclusive scan
    for (int d = 1; d < SCAN_T; d <<= 1) {
        int v = (t >= d) ? ssum[t - d] : 0;
        __syncthreads();
        ssum[t] += v;
        __syncthreads();
    }
    int run = ssum[t] - s;                 // exclusive prefix for this chunk
    for (int i = 0; i < CHUNK; i++) {
        int n = start + i;
        if (n < N_NODES) {
            g_off[n] = run;
            g_cur[n] = run;
            run += g_deg[n];
        }
    }
    if (t == SCAN_T - 1) g_off[N_NODES] = N_EDGES;
}

__global__ void fill_csr(const int* __restrict__ ei) {
    int e = blockIdx.x * blockDim.x + threadIdx.x;
    if (e < N_EDGES) {
        int dst = __ldg(&ei[N_EDGES + e]);
        int p = atomicAdd(&g_cur[dst], 1);
        g_elist[p] = __ldg(&ei[e]);
    }
}

// ---------------- aggregation: warp per node, register accumulate ---------
__global__ void aggregate(const float* __restrict__ x_ext, int use_h) {
    int t = blockIdx.x * blockDim.x + threadIdx.x;
    int w = t >> 5;
    int lane = t & 31;
    if (w >= N_NODES) return;
    const float* feat = use_h ? (const float*)g_h : x_ext;
    int o0 = g_off[w], o1 = g_off[w + 1];
    float4 s = make_float4(0.f, 0.f, 0.f, 0.f);
#pragma unroll 4
    for (int i = o0; i < o1; i++) {
        int src = __ldg(&g_elist[i]);
        float4 v = *(const float4*)(feat + (size_t)src * 128 + lane * 4);
        s.x += v.x; s.y += v.y; s.z += v.z; s.w += v.w;
    }
    int d = o1 - o0;
    float inv = (d > 0) ? (1.f / (float)d) : 0.f;
    s.x *= inv; s.y *= inv; s.z *= inv; s.w *= inv;
    *(float4*)(g_agg + (size_t)w * 128 + lane * 4) = s;
}

// ---------------- packed fp32x2 FMA helper ----------------
__device__ __forceinline__ void ffma2(unsigned long long& c,
                                      unsigned long long a, unsigned long long b) {
    asm("fma.rn.f32x2 %0, %1, %2, %0;" : "+l"(c) : "l"(a), "l"(b));
}
__device__ __forceinline__ float lo32(unsigned long long v) {
    return __uint_as_float((unsigned)(v & 0xffffffffull));
}
__device__ __forceinline__ float hi32(unsigned long long v) {
    return __uint_as_float((unsigned)(v >> 32));
}

// ---------------- fused GEMM:  C = [agg | A2] @ B (+bias, opt. relu) ------
// f32x2 path: a-pairs along M (natural from k-major As), b duplicated (b,b).
// LAYER==1: A2 = x (ext), Bdup = g_B1d [256x256], C = g_h, relu
// LAYER==2: A2 = g_h,     Bdup = g_B2d [256x128], C = Cext, no relu
template <int LAYER>
__global__ void __launch_bounds__(256, 2)
gemm_fused(const float* __restrict__ A2ext, const float* __restrict__ bias,
           float* __restrict__ Cext) {
    constexpr int BN = (LAYER == 1) ? 128 : 64;   // logical cols per block
    constexpr int NN = (LAYER == 1) ? 8 : 4;      // n values per thread
    constexpr int BM = 128;
    constexpr int BK = 32;
    constexpr int BW = 2 * BN;                    // dup width (floats)

    const float* Bd = (LAYER == 1) ? g_B1d : g_B2d;
    const float* A2 = (LAYER == 1) ? A2ext : (const float*)g_h;
    float*       C  = (LAYER == 1) ? g_h   : Cext;

    __shared__ float As[BK * BM];                 // k-major: As[k][m]
    __shared__ float Bs[BK * BW];                 // k-major dup: Bs[k][2o]

    int t  = threadIdx.x;
    int tx = t & 15;
    int ty = t >> 4;
    int m0 = blockIdx.x * BM;

    int m_stage = t & 127;
    int node_stage = m0 + m_stage;

    unsigned long long acc[4][NN];                // 4 m-pairs x NN n-cols
#pragma unroll
    for (int i = 0; i < 4; i++)
#pragma unroll
        for (int j = 0; j < NN; j++) acc[i][j] = 0ull;

    for (int kc = 0; kc < 256; kc += BK) {
        // ---- stage A tile (k-major) ----
#pragma unroll
        for (int q = 0; q < 4; q++) {
            int k  = ((t >> 7) + q * 2) * 4;      // 0,8,16,24 (+4 for upper half)
            int kg = kc + k;
            float4 v = make_float4(0.f, 0.f, 0.f, 0.f);
            if (node_stage < N_NODES) {
                if (kg < 128)
                    v = *(const float4*)(g_agg + (size_t)node_stage * 128 + kg);
                else
                    v = *(const float4*)(A2 + (size_t)node_stage * 128 + (kg - 128));
            }
            As[(k + 0) * BM + m_stage] = v.x;
            As[(k + 1) * BM + m_stage] = v.y;
            As[(k + 2) * BM + m_stage] = v.z;
            As[(k + 3) * BM + m_stage] = v.w;
        }
        // ---- stage B tile (contiguous, already duplicated) ----
        constexpr int NB4 = BK * BW / 4 / 256;    // 8 (L1) or 4 (L2)
#pragma unroll
        for (int q = 0; q < NB4; q++) {
            int idx = t + q * 256;
            ((float4*)Bs)[idx] = ((const float4*)(Bd + (size_t)kc * BW))[idx];
        }
        __syncthreads();

        // ---- compute: f32x2 ----
#pragma unroll
        for (int k = 0; k < BK; k++) {
            ulonglong2 A0 = *(const ulonglong2*)&As[k * BM + 4 * ty];
            ulonglong2 A1 = *(const ulonglong2*)&As[k * BM + 4 * ty + 64];
            unsigned long long a[4] = {A0.x, A0.y, A1.x, A1.y};
            unsigned long long b[NN];
            {
                ulonglong2 B0 = *(const ulonglong2*)&Bs[k * BW + 8 * tx];
                ulonglong2 B1 = *(const ulonglong2*)&Bs[k * BW + 8 * tx + 4];
                b[0] = B0.x; b[1] = B0.y; b[2] = B1.x; b[3] = B1.y;
                if (NN == 8) {
                    ulonglong2 B2 = *(const ulonglong2*)&Bs[k * BW + 8 * tx + 128];
                    ulonglong2 B3 = *(const ulonglong2*)&Bs[k * BW + 8 * tx + 132];
                    b[4] = B2.x; b[5] = B2.y; b[6] = B3.x; b[7] = B3.y;
                }
            }
#pragma unroll
            for (int i = 0; i < 4; i++)
#pragma unroll
                for (int j = 0; j < NN; j++)
                    ffma2(acc[i][j], a[i], b[j]);
        }
        __syncthreads();
    }

    // ---- epilogue: bias (+relu for layer 1) ----
#pragma unroll
    for (int i = 0; i < 4; i++) {
        int m_lo = m0 + 4 * ty + (i & 1) * 2 + (i >> 1) * 64;  // pair rows m_lo, m_lo+1
#pragma unroll
        for (int j = 0; j < NN; j++) {
            int c = 4 * tx + (j & 3) + (j >> 2) * 64;
            float bv = bias[c];
            float v0 = lo32(acc[i][j]) + bv;
            float v1 = hi32(acc[i][j]) + bv;
            if (LAYER == 1) { v0 = fmaxf(v0, 0.f); v1 = fmaxf(v1, 0.f); }
            if (m_lo < N_NODES)     C[(size_t)m_lo * BN + c] = v0;
            if (m_lo + 1 < N_NODES) C[(size_t)(m_lo + 1) * BN + c] = v1;
        }
    }
}

// ---------------- launcher ----------------
extern "C" void kernel_launch(void* const* d_in, const int* in_sizes, int n_in,
                              void* d_out, int out_size) {
    const float* x   = (const float*)d_in[0];
    const int*   ei  = (const int*)d_in[1];       // int32 (JAX x64 disabled)
    const float* W1l = (const float*)d_in[2];
    const float* b1l = (const float*)d_in[3];
    const float* W1r = (const float*)d_in[4];
    const float* W2l = (const float*)d_in[5];
    const float* b2l = (const float*)d_in[6];
    const float* W2r = (const float*)d_in[7];
    float* out = (float*)d_out;

    const int T = 256;
    int g_prep  = (256 * 128 + 256 * 64 + T - 1) / T;
    int g_node  = (N_NODES + T - 1) / T;
    int g_edge  = (N_EDGES + T - 1) / T;
    int g_aggr  = (N_NODES * 32 + T - 1) / T;
    int g_gemm  = (N_NODES + 127) / 128;

    prep_weights<<<g_prep, T>>>(W1l, W1r, W2l, W2r);

    // CSR build (once; same graph both layers)
    zero_deg<<<g_node, T>>>();
    count_deg<<<g_edge, T>>>(ei);
    scan_deg<<<1, SCAN_T>>>();
    fill_csr<<<g_edge, T>>>(ei);

    // ---- layer 1 ----
    aggregate<<<g_aggr, T>>>(x, 0);
    gemm_fused<1><<<g_gemm, T>>>(x, b1l, nullptr);

    // ---- layer 2 ----
    aggregate<<<g_aggr, T>>>(nullptr, 1);
    gemm_fused<2><<<g_gemm, T>>>(nullptr, b2l, out);
}

// round 6
// speedup vs baseline: 1.2264x; 1.2264x over previous
#include <cuda_runtime.h>

#define N_NODES 50000
#define N_EDGES 800000
#define SCAN_BT 512
#define SCAN_NB ((N_NODES + SCAN_BT - 1) / SCAN_BT)   // 98

// ---------------- scratch (no allocation allowed) ----------------
__device__ float g_agg[N_NODES * 128];   // normalized aggregation (both layers)
__device__ float g_h  [N_NODES * 128];   // layer-1 hidden activations
__device__ int   g_deg[N_NODES];         // in-degree
__device__ int   g_off[N_NODES + 1];     // CSR offsets (by dst)
__device__ int   g_cur[N_NODES];         // fill cursors
__device__ int   g_bsum[128];            // per-block sums for two-level scan
__device__ int   g_elist[N_EDGES];       // src list grouped by dst
__device__ float g_B1d[256 * 256];       // [W1l;W1r]^T k-major, DUPLICATED cols
__device__ float g_B2d[256 * 128];       // [W2l;W2r]^T k-major, DUPLICATED cols

// ---------------- weight prep: concatenated k-major B, each value dup'd ----
__global__ void prep_weights(const float* __restrict__ W1l, const float* __restrict__ W1r,
                             const float* __restrict__ W2l, const float* __restrict__ W2r) {
    int t = blockIdx.x * blockDim.x + threadIdx.x;
    if (t < 256 * 128) {
        int k = t >> 7, o = t & 127;
        float v = (k < 128) ? W1l[o * 128 + k] : W1r[o * 128 + (k - 128)];
        g_B1d[k * 256 + 2 * o] = v;
        g_B1d[k * 256 + 2 * o + 1] = v;
    } else if (t < 256 * 128 + 256 * 64) {
        int t2 = t - 256 * 128;
        int k = t2 >> 6, o = t2 & 63;
        float v = (k < 128) ? W2l[o * 128 + k] : W2r[o * 128 + (k - 128)];
        g_B2d[k * 128 + 2 * o] = v;
        g_B2d[k * 128 + 2 * o + 1] = v;
    }
}

// ---------------- CSR build ----------------
__global__ void zero_deg() {
    int t = blockIdx.x * blockDim.x + threadIdx.x;
    if (t < N_NODES) g_deg[t] = 0;
}

__global__ void count_deg(const int* __restrict__ ei) {
    int e = blockIdx.x * blockDim.x + threadIdx.x;
    if (e < N_EDGES) atomicAdd(&g_deg[__ldg(&ei[N_EDGES + e])], 1);
}

// two-level scan, all coalesced
__global__ void scan_blocks() {          // 98 blocks x 512 threads
    __shared__ int sh[SCAN_BT];
    int t = threadIdx.x;
    int n = blockIdx.x * SCAN_BT + t;
    int v = (n < N_NODES) ? g_deg[n] : 0;
    sh[t] = v;
    __syncthreads();
#pragma unroll
    for (int d = 1; d < SCAN_BT; d <<= 1) {
        int u = (t >= d) ? sh[t - d] : 0;
        __syncthreads();
        sh[t] += u;
        __syncthreads();
    }
    if (n < N_NODES) g_off[n] = sh[t] - v;            // local exclusive prefix
    if (t == SCAN_BT - 1) g_bsum[blockIdx.x] = sh[t]; // block total
}

__global__ void scan_bsums() {           // 1 block x 128 threads
    __shared__ int sh[128];
    int t = threadIdx.x;
    int v = (t < SCAN_NB) ? g_bsum[t] : 0;
    sh[t] = v;
    __syncthreads();
#pragma unroll
    for (int d = 1; d < 128; d <<= 1) {
        int u = (t >= d) ? sh[t - d] : 0;
        __syncthreads();
        sh[t] += u;
        __syncthreads();
    }
    if (t < SCAN_NB) g_bsum[t] = sh[t] - v;           // exclusive block prefix
}

__global__ void apply_bsums() {          // 98 blocks x 512 threads
    int t = threadIdx.x;
    int n = blockIdx.x * SCAN_BT + t;
    if (n < N_NODES) {
        int o = g_off[n] + g_bsum[blockIdx.x];
        g_off[n] = o;
        g_cur[n] = o;
    }
    if (blockIdx.x == 0 && t == 0) g_off[N_NODES] = N_EDGES;
}

__global__ void fill_csr(const int* __restrict__ ei) {
    int e = blockIdx.x * blockDim.x + threadIdx.x;
    if (e < N_EDGES) {
        int dst = __ldg(&ei[N_EDGES + e]);
        int p = atomicAdd(&g_cur[dst], 1);
        g_elist[p] = __ldg(&ei[e]);
    }
}

// ---------------- aggregation: warp per node, register accumulate ---------
__global__ void aggregate(const float* __restrict__ x_ext, int use_h) {
    int t = blockIdx.x * blockDim.x + threadIdx.x;
    int w = t >> 5;
    int lane = t & 31;
    if (w >= N_NODES) return;
    const float* feat = use_h ? (const float*)g_h : x_ext;
    int o0 = g_off[w], o1 = g_off[w + 1];
    float4 s = make_float4(0.f, 0.f, 0.f, 0.f);
#pragma unroll 4
    for (int i = o0; i < o1; i++) {
        int src = __ldg(&g_elist[i]);
        float4 v = *(const float4*)(feat + (size_t)src * 128 + lane * 4);
        s.x += v.x; s.y += v.y; s.z += v.z; s.w += v.w;
    }
    int d = o1 - o0;
    float inv = (d > 0) ? (1.f / (float)d) : 0.f;
    s.x *= inv; s.y *= inv; s.z *= inv; s.w *= inv;
    *(float4*)(g_agg + (size_t)w * 128 + lane * 4) = s;
}

// ---------------- packed fp32x2 FMA helper ----------------
__device__ __forceinline__ void ffma2(unsigned long long& c,
                                      unsigned long long a, unsigned long long b) {
    asm("fma.rn.f32x2 %0, %1, %2, %0;" : "+l"(c) : "l"(a), "l"(b));
}
__device__ __forceinline__ float lo32(unsigned long long v) {
    return __uint_as_float((unsigned)(v & 0xffffffffull));
}
__device__ __forceinline__ float hi32(unsigned long long v) {
    return __uint_as_float((unsigned)(v >> 32));
}

// ---------------- fused GEMM:  C = [agg | A2] @ B (+bias, opt. relu) ------
template <int LAYER>
__global__ void __launch_bounds__(256, 2)
gemm_fused(const float* __restrict__ A2ext, const float* __restrict__ bias,
           float* __restrict__ Cext) {
    constexpr int BN = (LAYER == 1) ? 128 : 64;   // logical cols per block
    constexpr int NN = (LAYER == 1) ? 8 : 4;      // n values per thread
    constexpr int BM = 128;
    constexpr int BK = 32;
    constexpr int BW = 2 * BN;                    // dup width (floats)

    const float* Bd = (LAYER == 1) ? g_B1d : g_B2d;
    const float* A2 = (LAYER == 1) ? A2ext : (const float*)g_h;
    float*       C  = (LAYER == 1) ? g_h   : Cext;

    __shared__ float As[BK * BM];                 // k-major: As[k][m]
    __shared__ float Bs[BK * BW];                 // k-major dup: Bs[k][2o]

    int t  = threadIdx.x;
    int tx = t & 15;
    int ty = t >> 4;
    int m0 = blockIdx.x * BM;

    int m_stage = t & 127;
    int node_stage = m0 + m_stage;

    unsigned long long acc[4][NN];                // 4 m-pairs x NN n-cols
#pragma unroll
    for (int i = 0; i < 4; i++)
#pragma unroll
        for (int j = 0; j < NN; j++) acc[i][j] = 0ull;

    for (int kc = 0; kc < 256; kc += BK) {
        // ---- stage A tile (k-major) ----
#pragma unroll
        for (int q = 0; q < 4; q++) {
            int k  = ((t >> 7) + q * 2) * 4;
            int kg = kc + k;
            float4 v = make_float4(0.f, 0.f, 0.f, 0.f);
            if (node_stage < N_NODES) {
                if (kg < 128)
                    v = *(const float4*)(g_agg + (size_t)node_stage * 128 + kg);
                else
                    v = *(const float4*)(A2 + (size_t)node_stage * 128 + (kg - 128));
            }
            As[(k + 0) * BM + m_stage] = v.x;
            As[(k + 1) * BM + m_stage] = v.y;
            As[(k + 2) * BM + m_stage] = v.z;
            As[(k + 3) * BM + m_stage] = v.w;
        }
        // ---- stage B tile (contiguous, already duplicated) ----
        constexpr int NB4 = BK * BW / 4 / 256;    // 8 (L1) or 4 (L2)
#pragma unroll
        for (int q = 0; q < NB4; q++) {
            int idx = t + q * 256;
            ((float4*)Bs)[idx] = ((const float4*)(Bd + (size_t)kc * BW))[idx];
        }
        __syncthreads();

        // ---- compute: f32x2 ----
#pragma unroll
        for (int k = 0; k < BK; k++) {
            ulonglong2 A0 = *(const ulonglong2*)&As[k * BM + 4 * ty];
            ulonglong2 A1 = *(const ulonglong2*)&As[k * BM + 4 * ty + 64];
            unsigned long long a[4] = {A0.x, A0.y, A1.x, A1.y};
            unsigned long long b[NN];
            {
                ulonglong2 B0 = *(const ulonglong2*)&Bs[k * BW + 8 * tx];
                ulonglong2 B1 = *(const ulonglong2*)&Bs[k * BW + 8 * tx + 4];
                b[0] = B0.x; b[1] = B0.y; b[2] = B1.x; b[3] = B1.y;
                if (NN == 8) {
                    ulonglong2 B2 = *(const ulonglong2*)&Bs[k * BW + 8 * tx + 128];
                    ulonglong2 B3 = *(const ulonglong2*)&Bs[k * BW + 8 * tx + 132];
                    b[4] = B2.x; b[5] = B2.y; b[6] = B3.x; b[7] = B3.y;
                }
            }
#pragma unroll
            for (int i = 0; i < 4; i++)
#pragma unroll
                for (int j = 0; j < NN; j++)
                    ffma2(acc[i][j], a[i], b[j]);
        }
        __syncthreads();
    }

    // ---- epilogue: bias (+relu for layer 1) ----
#pragma unroll
    for (int i = 0; i < 4; i++) {
        int m_lo = m0 + 4 * ty + (i & 1) * 2 + (i >> 1) * 64;
#pragma unroll
        for (int j = 0; j < NN; j++) {
            int c = 4 * tx + (j & 3) + (j >> 2) * 64;
            float bv = bias[c];
            float v0 = lo32(acc[i][j]) + bv;
            float v1 = hi32(acc[i][j]) + bv;
            if (LAYER == 1) { v0 = fmaxf(v0, 0.f); v1 = fmaxf(v1, 0.f); }
            if (m_lo < N_NODES)     C[(size_t)m_lo * BN + c] = v0;
            if (m_lo + 1 < N_NODES) C[(size_t)(m_lo + 1) * BN + c] = v1;
        }
    }
}

// ---------------- launcher ----------------
extern "C" void kernel_launch(void* const* d_in, const int* in_sizes, int n_in,
                              void* d_out, int out_size) {
    const float* x   = (const float*)d_in[0];
    const int*   ei  = (const int*)d_in[1];       // int32 (JAX x64 disabled)
    const float* W1l = (const float*)d_in[2];
    const float* b1l = (const float*)d_in[3];
    const float* W1r = (const float*)d_in[4];
    const float* W2l = (const float*)d_in[5];
    const float* b2l = (const float*)d_in[6];
    const float* W2r = (const float*)d_in[7];
    float* out = (float*)d_out;

    const int T = 256;
    int g_prep  = (256 * 128 + 256 * 64 + T - 1) / T;
    int g_node  = (N_NODES + T - 1) / T;
    int g_edge  = (N_EDGES + T - 1) / T;
    int g_aggr  = (N_NODES * 32 + T - 1) / T;
    int g_gemm  = (N_NODES + 127) / 128;

    prep_weights<<<g_prep, T>>>(W1l, W1r, W2l, W2r);

    // CSR build (once; same graph both layers)
    zero_deg<<<g_node, T>>>();
    count_deg<<<g_edge, T>>>(ei);
    scan_blocks<<<SCAN_NB, SCAN_BT>>>();
    scan_bsums<<<1, 128>>>();
    apply_bsums<<<SCAN_NB, SCAN_BT>>>();
    fill_csr<<<g_edge, T>>>(ei);

    // ---- layer 1 ----
    aggregate<<<g_aggr, T>>>(x, 0);
    gemm_fused<1><<<g_gemm, T>>>(x, b1l, nullptr);

    // ---- layer 2 ----
    aggregate<<<g_aggr, T>>>(nullptr, 1);
    gemm_fused<2><<<g_gemm, T>>>(nullptr, b2l, out);
}